// round 3
// baseline (speedup 1.0000x reference)
#include <cuda_runtime.h>
#include <cstdint>

#define NTHREADS 256
#define NWARPS   (NTHREADS / 32)

typedef unsigned long long ull;

// Per-row loss scratch (device global: allocation-free, graph-safe).
__device__ float g_L[4096];
__device__ int   g_is64;

// ---------- f32x2 packed helpers (sm_103a) ----------
__device__ __forceinline__ ull pk2(float lo, float hi) {
    ull r; asm("mov.b64 %0, {%1,%2};" : "=l"(r) : "f"(lo), "f"(hi)); return r;
}
__device__ __forceinline__ void upk2(ull v, float& lo, float& hi) {
    asm("mov.b64 {%0,%1}, %2;" : "=f"(lo), "=f"(hi) : "l"(v));
}
__device__ __forceinline__ ull add2(ull a, ull b) {
    ull r; asm("add.rn.f32x2 %0, %1, %2;" : "=l"(r) : "l"(a), "l"(b)); return r;
}
__device__ __forceinline__ ull mul2(ull a, ull b) {
    ull r; asm("mul.rn.f32x2 %0, %1, %2;" : "=l"(r) : "l"(a), "l"(b)); return r;
}
__device__ __forceinline__ ull fma2(ull a, ull b, ull c) {
    ull r; asm("fma.rn.f32x2 %0, %1, %2, %3;" : "=l"(r) : "l"(a), "l"(b), "l"(c)); return r;
}
__device__ __forceinline__ float ex2f_(float a) {
    float r; asm("ex2.approx.ftz.f32 %0, %1;" : "=f"(r) : "f"(a)); return r;
}
__device__ __forceinline__ float lg_(float a) {  // natural log
    float r; asm("lg2.approx.ftz.f32 %0, %1;" : "=f"(r) : "f"(a));
    return r * 0.6931471805599453f;
}

// Detect whether targets buffer is int64 or int32 (LE: odd int32 words zero).
__global__ void aed_detect_kernel(const int* __restrict__ t, int B) {
    int lane = threadIdx.x & 31;
    int n = B < 128 ? B : 128;
    bool ok = true;
    for (int i = lane; i < n; i += 32) ok &= (t[2 * i + 1] == 0);
    unsigned m = __ballot_sync(0xffffffffu, ok);
    if (lane == 0 && blockIdx.x == 0) g_is64 = (m == 0xffffffffu) ? 1 : 0;
}

union F4U { float4 f; ull u[2]; };

__global__ __launch_bounds__(NTHREADS)
void aed_row_kernel(const float* __restrict__ o0, const float* __restrict__ o1,
                    const float* __restrict__ o2, const float* __restrict__ o3,
                    const void* __restrict__ targets,
                    float* __restrict__ out, int C)
{
    const int b   = blockIdx.x;
    const int tid = threadIdx.x;

    const float4* p0 = (const float4*)(o0 + (size_t)b * C);
    const float4* p1 = (const float4*)(o1 + (size_t)b * C);
    const float4* p2 = (const float4*)(o2 + (size_t)b * C);
    const float4* p3 = (const float4*)(o3 + (size_t)b * C);
    float* mout = out + 1 + (size_t)b * C;  // mimic row; 4-byte aligned ONLY

    const int tgti = g_is64 ? (int)(((const long long*)targets)[b])
                            : ((const int*)targets)[b];

    // packed constants
    const float Kf = 0.48089834696298783f;           // log2(e)/3
    const ull K2     = pk2(Kf, Kf);
    const ull negone = pk2(-1.f, -1.f);
    const ull quart  = pk2(0.25f, 0.25f);
    const ull c15    = pk2(1.f / 15.f, 1.f / 15.f);  // u = (m-x)*0.2/3
    const ull c24    = pk2(1.f / 24.f, 1.f / 24.f);
    const ull c6     = pk2(1.f / 6.f, 1.f / 6.f);
    const ull chalf  = pk2(0.5f, 0.5f);
    const ull one2   = pk2(1.f, 1.f);

    // packed accumulators (pair of column-halves each)
    ull Z1[4], ZS[4], ZT[4], WT[4], D[10];
#pragma unroll
    for (int j = 0; j < 4; j++) { Z1[j] = 0; ZS[j] = 0; ZT[j] = 0; WT[j] = 0; }
#pragma unroll
    for (int d = 0; d < 10; d++) D[d] = 0;

    __shared__ float s_xt[4];
    __shared__ float sred[NWARPS][26];

    const int C4 = C >> 2;

    for (int i = tid; i < C4; i += NTHREADS) {
        F4U a, bq, cq, dq, mo;
        a.f  = __ldcs(p0 + i);
        bq.f = __ldcs(p1 + i);
        cq.f = __ldcs(p2 + i);
        dq.f = __ldcs(p3 + i);

#pragma unroll
        for (int h = 0; h < 2; h++) {
            ull X0 = a.u[h], X1 = bq.u[h], X2 = cq.u[h], X3 = dq.u[h];
            ull M = mul2(add2(add2(X0, X1), add2(X2, X3)), quart);
            mo.u[h] = M;

            D[0] = fma2(X0, X0, D[0]);
            D[1] = fma2(X0, X1, D[1]);
            D[2] = fma2(X0, X2, D[2]);
            D[3] = fma2(X0, X3, D[3]);
            D[4] = fma2(X1, X1, D[4]);
            D[5] = fma2(X1, X2, D[5]);
            D[6] = fma2(X1, X3, D[6]);
            D[7] = fma2(X2, X2, D[7]);
            D[8] = fma2(X2, X3, D[8]);
            D[9] = fma2(X3, X3, D[9]);

            ull Xj[4] = {X0, X1, X2, X3};
#pragma unroll
            for (int j = 0; j < 4; j++) {
                ull arg = mul2(Xj[j], K2);                 // x * log2(e)/3
                float a0, a1; upk2(arg, a0, a1);
                float e0 = ex2f_(a0), e1 = ex2f_(a1);      // e = exp(x/3)
                ull E  = pk2(e0, e1);
                ull E2 = mul2(E, E);
                ull E3 = mul2(E2, E);                      // exp(x)
                Z1[j] = add2(Z1[j], E3);
                ZS[j] = add2(ZS[j], E);

                ull DM = fma2(Xj[j], negone, M);           // m - x
                ull U  = mul2(DM, c15);                    // |u| <= ~0.35
                ull P  = fma2(c24, U, c6);
                P = fma2(P, U, chalf);
                P = fma2(P, U, one2);
                P = fma2(P, U, one2);                      // exp(u), deg-4 Taylor
                ull ET = mul2(E, P);                       // exp(t/3)
                ZT[j] = add2(ZT[j], ET);
                WT[j] = fma2(ET, DM, WT[j]);
            }
        }

        // mimic row base is out+1 -> 4-byte aligned only: scalar stores
        int cbase = i << 2;
        const float* mf = (const float*)&mo.f;
        __stcs(mout + cbase + 0, mf[0]);
        __stcs(mout + cbase + 1, mf[1]);
        __stcs(mout + cbase + 2, mf[2]);
        __stcs(mout + cbase + 3, mf[3]);

        unsigned dv = (unsigned)(tgti - cbase);
        if (dv < 4u) {
            const float* fa = (const float*)&a.f;
            const float* fb = (const float*)&bq.f;
            const float* fc = (const float*)&cq.f;
            const float* fd = (const float*)&dq.f;
            s_xt[0] = fa[dv]; s_xt[1] = fb[dv]; s_xt[2] = fc[dv]; s_xt[3] = fd[dv];
        }
    }

    // collapse packed halves -> 26 scalars
    float r[26];
#pragma unroll
    for (int j = 0; j < 4; j++) {
        float lo, hi;
        upk2(Z1[j], lo, hi); r[j]      = lo + hi;
        upk2(ZS[j], lo, hi); r[4 + j]  = lo + hi;
        upk2(ZT[j], lo, hi); r[8 + j]  = lo + hi;
        upk2(WT[j], lo, hi); r[12 + j] = lo + hi;
    }
#pragma unroll
    for (int d = 0; d < 10; d++) {
        float lo, hi;
        upk2(D[d], lo, hi); r[16 + d] = lo + hi;
    }

    // warp tree-reduce (plain sums: no max state)
    const unsigned FULL = 0xffffffffu;
#pragma unroll
    for (int off = 16; off > 0; off >>= 1)
#pragma unroll
        for (int k = 0; k < 26; k++)
            r[k] += __shfl_down_sync(FULL, r[k], off);

    int lane = tid & 31, wid = tid >> 5;
    if (lane == 0)
#pragma unroll
        for (int k = 0; k < 26; k++) sred[wid][k] = r[k];
    __syncthreads();

    if (tid == 0) {
        for (int w = 1; w < NWARPS; w++)
#pragma unroll
            for (int k = 0; k < 26; k++) r[k] += sred[w][k];

        float xt[4] = {s_xt[0], s_xt[1], s_xt[2], s_xt[3]};
        const float invC = 1.0f / (float)C;
        float CE[4], KD[4];
#pragma unroll
        for (int j = 0; j < 4; j++) {
            float lse1 = lg_(r[j]);          // logsumexp(x),   M=0
            float lses = lg_(r[4 + j]);      // logsumexp(x/T)
            float lset = lg_(r[8 + j]);      // logsumexp(t/T)
            CE[j] = lse1 - xt[j];
            float S = r[12 + j] / r[8 + j];  // sum_c p_t*(m - x)
            KD[j] = 9.0f * invC * ((0.2f / 3.f) * S + lses - lset);
        }

        // DAL: deleting target entry == subtract xt_j*xt_k from dot accums
        float dd[10];
        int idx = 0;
#pragma unroll
        for (int j = 0; j < 4; j++)
#pragma unroll
            for (int k = j; k < 4; k++) { dd[idx] = r[16 + idx] - xt[j] * xt[k]; idx++; }
        float n0 = sqrtf(dd[0]), n1 = sqrtf(dd[4]), n2 = sqrtf(dd[7]), n3 = sqrtf(dd[9]);
        float dal = dd[1] / (n0 * n1) + dd[2] / (n0 * n2) + dd[3] / (n0 * n3)
                  + dd[5] / (n1 * n2) + dd[6] / (n1 * n3) + dd[8] / (n2 * n3);

        float irm = 0.f, mn = 3.402823466e38f;
#pragma unroll
        for (int j = 0; j < 4; j++) { irm += CE[j] + KD[j]; mn = fminf(mn, CE[j]); }
        g_L[b] = irm + 0.7f * mn + 0.3f * dal;
    }
}

__global__ void aed_final_kernel(float* __restrict__ out, int B) {
    __shared__ float s[NTHREADS];
    float a = 0.f;
    for (int i = threadIdx.x; i < B; i += NTHREADS) a += g_L[i];
    s[threadIdx.x] = a;
    __syncthreads();
    for (int st = NTHREADS / 2; st > 0; st >>= 1) {
        if (threadIdx.x < st) s[threadIdx.x] += s[threadIdx.x + st];
        __syncthreads();
    }
    if (threadIdx.x == 0) out[0] = s[0] / (float)B;
}

extern "C" void kernel_launch(void* const* d_in, const int* in_sizes, int n_in,
                              void* d_out, int out_size) {
    const float* o0 = (const float*)d_in[0];
    const float* o1 = (const float*)d_in[1];
    const float* o2 = (const float*)d_in[2];
    const float* o3 = (const float*)d_in[3];
    const void*  tg = d_in[4];
    const int B = in_sizes[4];
    const int C = in_sizes[0] / B;
    float* out = (float*)d_out;

    aed_detect_kernel<<<1, 32>>>((const int*)tg, B);
    aed_row_kernel<<<B, NTHREADS>>>(o0, o1, o2, o3, tg, out, C);
    aed_final_kernel<<<1, NTHREADS>>>(out, B);
}

// round 4
// speedup vs baseline: 1.4075x; 1.4075x over previous
#include <cuda_runtime.h>
#include <cstdint>

#define NTHREADS 256
#define NWARPS   (NTHREADS / 32)

// Per-row loss scratch + completion counter (device globals: allocation-free).
__device__ float    g_L[4096];
__device__ unsigned g_cnt = 0;

__device__ __forceinline__ float ex2f_(float a) {
    float r; asm("ex2.approx.ftz.f32 %0, %1;" : "=f"(r) : "f"(a)); return r;
}
__device__ __forceinline__ float lg_(float a) {  // natural log
    float r; asm("lg2.approx.ftz.f32 %0, %1;" : "=f"(r) : "f"(a));
    return r * 0.6931471805599453f;
}

__global__ __launch_bounds__(NTHREADS, 2)
void aed_fused_kernel(const float* __restrict__ o0, const float* __restrict__ o1,
                      const float* __restrict__ o2, const float* __restrict__ o3,
                      const void* __restrict__ targets,
                      float* __restrict__ out, int C, int B)
{
    __shared__ float s_xt[4];
    __shared__ float sred[NWARPS][26];
    __shared__ int   s_is64;
    __shared__ int   s_last;

    const int b   = blockIdx.x;
    const int tid = threadIdx.x;

    // ---- inline targets-dtype detect (int64 LE: odd int32 words all zero) ----
    if (tid < 32) {
        const int* t32 = (const int*)targets;
        int n = B < 128 ? B : 128;
        bool ok = true;
        for (int i = tid; i < n; i += 32) ok &= (t32[2 * i + 1] == 0);
        unsigned msk = __ballot_sync(0xffffffffu, ok);
        if (tid == 0) s_is64 = (msk == 0xffffffffu);
    }
    __syncthreads();
    const int tgti = s_is64 ? (int)(((const long long*)targets)[b])
                            : ((const int*)targets)[b];

    const float4* p0 = (const float4*)(o0 + (size_t)b * C);
    const float4* p1 = (const float4*)(o1 + (size_t)b * C);
    const float4* p2 = (const float4*)(o2 + (size_t)b * C);
    const float4* p3 = (const float4*)(o3 + (size_t)b * C);
    float* mout = out + 1 + (size_t)b * C;  // mimic row; 4-byte aligned ONLY

    const float K   = 0.48089834696298783f;   // log2(e)/3
    const float LG  = 1.4426950408889634f;    // log2(e)
    const float K02 = 0.2f * 0.48089834696298783f;

    // accumulators: z1 = sum e^x, zs = sum e^(x/3), zt = sum e^(t/3),
    // wt = sum e^(t/3)*(m-x), D = Gram dots
    float z1[4], zs[4], zt[4], wt[4], D[10];
#pragma unroll
    for (int j = 0; j < 4; j++) { z1[j] = 0.f; zs[j] = 0.f; zt[j] = 0.f; wt[j] = 0.f; }
#pragma unroll
    for (int d = 0; d < 10; d++) D[d] = 0.f;

    const int C4 = C >> 2;

    for (int i = tid; i < C4; i += NTHREADS) {
        float4 a  = __ldcs(p0 + i);
        float4 bq = __ldcs(p1 + i);
        float4 cq = __ldcs(p2 + i);
        float4 dq = __ldcs(p3 + i);

        float x0v[4] = {a.x,  a.y,  a.z,  a.w};
        float x1v[4] = {bq.x, bq.y, bq.z, bq.w};
        float x2v[4] = {cq.x, cq.y, cq.z, cq.w};
        float x3v[4] = {dq.x, dq.y, dq.z, dq.w};
        float mv[4];

#pragma unroll
        for (int v = 0; v < 4; v++) {
            float x0 = x0v[v], x1 = x1v[v], x2 = x2v[v], x3 = x3v[v];
            float m = 0.25f * ((x0 + x1) + (x2 + x3));
            mv[v] = m;
            float km02 = m * K02;

            D[0] = fmaf(x0, x0, D[0]);
            D[1] = fmaf(x0, x1, D[1]);
            D[2] = fmaf(x0, x2, D[2]);
            D[3] = fmaf(x0, x3, D[3]);
            D[4] = fmaf(x1, x1, D[4]);
            D[5] = fmaf(x1, x2, D[5]);
            D[6] = fmaf(x1, x3, D[6]);
            D[7] = fmaf(x2, x2, D[7]);
            D[8] = fmaf(x2, x3, D[8]);
            D[9] = fmaf(x3, x3, D[9]);

            float xj[4] = {x0, x1, x2, x3};
#pragma unroll
            for (int j = 0; j < 4; j++) {
                float x    = xj[j];
                float arg3 = x * K;                      // x/3 * log2e
                float argF = x * LG;                     // x   * log2e
                float argT = fmaf(0.8f, arg3, km02);     // t/3 * log2e
                float e  = ex2f_(arg3);                  // exp(x/3)
                float E3 = ex2f_(argF);                  // exp(x)
                float et = ex2f_(argT);                  // exp(t/3)
                z1[j] += E3;
                zs[j] += e;
                zt[j] += et;
                wt[j]  = fmaf(et, m - x, wt[j]);
            }
        }

        // mimic row base is out+1 -> 4-byte aligned only: scalar stores
        int cbase = i << 2;
        __stcs(mout + cbase + 0, mv[0]);
        __stcs(mout + cbase + 1, mv[1]);
        __stcs(mout + cbase + 2, mv[2]);
        __stcs(mout + cbase + 3, mv[3]);

        unsigned dv = (unsigned)(tgti - cbase);
        if (dv < 4u) {
            s_xt[0] = x0v[dv]; s_xt[1] = x1v[dv];
            s_xt[2] = x2v[dv]; s_xt[3] = x3v[dv];
        }
    }

    // gather 26 partials
    float r[26];
#pragma unroll
    for (int j = 0; j < 4; j++) {
        r[j] = z1[j]; r[4 + j] = zs[j]; r[8 + j] = zt[j]; r[12 + j] = wt[j];
    }
#pragma unroll
    for (int d = 0; d < 10; d++) r[16 + d] = D[d];

    // warp tree-reduce (plain sums)
    const unsigned FULL = 0xffffffffu;
#pragma unroll
    for (int off = 16; off > 0; off >>= 1)
#pragma unroll
        for (int k = 0; k < 26; k++)
            r[k] += __shfl_down_sync(FULL, r[k], off);

    int lane = tid & 31, wid = tid >> 5;
    if (lane == 0)
#pragma unroll
        for (int k = 0; k < 26; k++) sred[wid][k] = r[k];
    __syncthreads();

    if (tid == 0) {
        for (int w = 1; w < NWARPS; w++)
#pragma unroll
            for (int k = 0; k < 26; k++) r[k] += sred[w][k];

        float xt[4] = {s_xt[0], s_xt[1], s_xt[2], s_xt[3]};
        const float invC = 1.0f / (float)C;
        float CE[4], KD[4];
#pragma unroll
        for (int j = 0; j < 4; j++) {
            float lse1 = lg_(r[j]);          // logsumexp(x),   M=0
            float lses = lg_(r[4 + j]);      // logsumexp(x/T)
            float lset = lg_(r[8 + j]);      // logsumexp(t/T)
            CE[j] = lse1 - xt[j];
            float S = r[12 + j] / r[8 + j];  // sum_c p_t*(m - x)
            KD[j] = 9.0f * invC * ((0.2f / 3.f) * S + lses - lset);
        }

        // DAL: deleting target entry == subtract xt_j*xt_k from dot accums
        float dd[10];
        int idx = 0;
#pragma unroll
        for (int j = 0; j < 4; j++)
#pragma unroll
            for (int k = j; k < 4; k++) { dd[idx] = r[16 + idx] - xt[j] * xt[k]; idx++; }
        float n0 = sqrtf(dd[0]), n1 = sqrtf(dd[4]), n2 = sqrtf(dd[7]), n3 = sqrtf(dd[9]);
        float dal = dd[1] / (n0 * n1) + dd[2] / (n0 * n2) + dd[3] / (n0 * n3)
                  + dd[5] / (n1 * n2) + dd[6] / (n1 * n3) + dd[8] / (n2 * n3);

        float irm = 0.f, mn = 3.402823466e38f;
#pragma unroll
        for (int j = 0; j < 4; j++) { irm += CE[j] + KD[j]; mn = fminf(mn, CE[j]); }
        g_L[b] = irm + 0.7f * mn + 0.3f * dal;
    }

    // ---- grid-wide finalize: last CTA to finish computes the mean ----
    __threadfence();
    if (tid == 0) {
        unsigned v = atomicAdd(&g_cnt, 1u);
        s_last = (v == (unsigned)(gridDim.x - 1));
    }
    __syncthreads();
    if (s_last) {
        __threadfence();  // acquire: see all g_L writes
        __shared__ float sf[NTHREADS];
        float acc = 0.f;
        for (int i = tid; i < B; i += NTHREADS) acc += g_L[i];
        sf[tid] = acc;
        __syncthreads();
        for (int st = NTHREADS / 2; st > 0; st >>= 1) {
            if (tid < st) sf[tid] += sf[tid + st];
            __syncthreads();
        }
        if (tid == 0) {
            out[0] = sf[0] / (float)B;
            g_cnt = 0;  // reset for next replay (deterministic)
        }
    }
}

extern "C" void kernel_launch(void* const* d_in, const int* in_sizes, int n_in,
                              void* d_out, int out_size) {
    const float* o0 = (const float*)d_in[0];
    const float* o1 = (const float*)d_in[1];
    const float* o2 = (const float*)d_in[2];
    const float* o3 = (const float*)d_in[3];
    const void*  tg = d_in[4];
    const int B = in_sizes[4];
    const int C = in_sizes[0] / B;
    float* out = (float*)d_out;

    aed_fused_kernel<<<B, NTHREADS>>>(o0, o1, o2, o3, tg, out, C, B);
}

// round 5
// speedup vs baseline: 1.4421x; 1.0245x over previous
#include <cuda_runtime.h>
#include <cstdint>

#define NTHREADS 512
#define NWARPS   (NTHREADS / 32)

// Per-row loss scratch + completion counter (device globals: allocation-free).
__device__ float    g_L[4096];
__device__ unsigned g_cnt = 0;

__device__ __forceinline__ float ex2f_(float a) {
    float r; asm("ex2.approx.ftz.f32 %0, %1;" : "=f"(r) : "f"(a)); return r;
}
__device__ __forceinline__ float lg_(float a) {  // natural log
    float r; asm("lg2.approx.ftz.f32 %0, %1;" : "=f"(r) : "f"(a));
    return r * 0.6931471805599453f;
}

__global__ __launch_bounds__(NTHREADS, 1)
void aed_fused_kernel(const float* __restrict__ o0, const float* __restrict__ o1,
                      const float* __restrict__ o2, const float* __restrict__ o3,
                      const void* __restrict__ targets,
                      float* __restrict__ out, int C, int B)
{
    __shared__ float s_xt[4];
    __shared__ float sred[NWARPS][26];
    __shared__ int   s_is64;
    __shared__ int   s_last;

    const int b   = blockIdx.x;
    const int tid = threadIdx.x;

    // ---- inline targets-dtype detect (int64 LE: odd int32 words all zero) ----
    if (tid < 32) {
        const int* t32 = (const int*)targets;
        int n = B < 128 ? B : 128;
        bool ok = true;
        for (int i = tid; i < n; i += 32) ok &= (t32[2 * i + 1] == 0);
        unsigned msk = __ballot_sync(0xffffffffu, ok);
        if (tid == 0) s_is64 = (msk == 0xffffffffu);
    }
    __syncthreads();
    const int tgti = s_is64 ? (int)(((const long long*)targets)[b])
                            : ((const int*)targets)[b];

    const float4* p0 = (const float4*)(o0 + (size_t)b * C);
    const float4* p1 = (const float4*)(o1 + (size_t)b * C);
    const float4* p2 = (const float4*)(o2 + (size_t)b * C);
    const float4* p3 = (const float4*)(o3 + (size_t)b * C);
    float* mout = out + 1 + (size_t)b * C;  // mimic row; 4-byte aligned ONLY

    const float K   = 0.48089834696298783f;   // log2(e)/3
    const float K02 = 0.2f * 0.48089834696298783f;

    // accumulators: z1 = sum e^x, zs = sum e^(x/3), zt = sum e^(t/3),
    // wt = sum e^(t/3)*(m-x), D = Gram dots
    float z1[4], zs[4], zt[4], wt[4], D[10];
#pragma unroll
    for (int j = 0; j < 4; j++) { z1[j] = 0.f; zs[j] = 0.f; zt[j] = 0.f; wt[j] = 0.f; }
#pragma unroll
    for (int d = 0; d < 10; d++) D[d] = 0.f;

    const int C4 = C >> 2;
    const float4 zf4 = make_float4(0.f, 0.f, 0.f, 0.f);

    // software pipeline: current tile in (a,bq,cq,dq), prefetch into (a2..dq2)
    int i = tid;
    float4 a  = (i < C4) ? __ldcs(p0 + i) : zf4;
    float4 bq = (i < C4) ? __ldcs(p1 + i) : zf4;
    float4 cq = (i < C4) ? __ldcs(p2 + i) : zf4;
    float4 dq = (i < C4) ? __ldcs(p3 + i) : zf4;

    while (i < C4) {
        const int ni  = i + NTHREADS;
        const bool hs = ni < C4;
        float4 a2  = hs ? __ldcs(p0 + ni) : zf4;
        float4 bq2 = hs ? __ldcs(p1 + ni) : zf4;
        float4 cq2 = hs ? __ldcs(p2 + ni) : zf4;
        float4 dq2 = hs ? __ldcs(p3 + ni) : zf4;

        float x0v[4] = {a.x,  a.y,  a.z,  a.w};
        float x1v[4] = {bq.x, bq.y, bq.z, bq.w};
        float x2v[4] = {cq.x, cq.y, cq.z, cq.w};
        float x3v[4] = {dq.x, dq.y, dq.z, dq.w};
        float mv[4];

#pragma unroll
        for (int v = 0; v < 4; v++) {
            float x0 = x0v[v], x1 = x1v[v], x2 = x2v[v], x3 = x3v[v];
            float m = 0.25f * ((x0 + x1) + (x2 + x3));
            mv[v] = m;
            float km02 = m * K02;

            D[0] = fmaf(x0, x0, D[0]);
            D[1] = fmaf(x0, x1, D[1]);
            D[2] = fmaf(x0, x2, D[2]);
            D[3] = fmaf(x0, x3, D[3]);
            D[4] = fmaf(x1, x1, D[4]);
            D[5] = fmaf(x1, x2, D[5]);
            D[6] = fmaf(x1, x3, D[6]);
            D[7] = fmaf(x2, x2, D[7]);
            D[8] = fmaf(x2, x3, D[8]);
            D[9] = fmaf(x3, x3, D[9]);

            float xj[4] = {x0, x1, x2, x3};
#pragma unroll
            for (int j = 0; j < 4; j++) {
                float x    = xj[j];
                float arg3 = x * K;                      // x/3 * log2e
                float argT = fmaf(0.8f, arg3, km02);     // t/3 * log2e
                float e  = ex2f_(arg3);                  // exp(x/3)
                float et = ex2f_(argT);                  // exp(t/3)
                float e3 = e * e * e;                    // exp(x) via cube (MUFU->FMA)
                z1[j] += e3;
                zs[j] += e;
                zt[j] += et;
                wt[j]  = fmaf(et, m - x, wt[j]);
            }
        }

        // mimic row base is out+1 -> 4-byte aligned only: scalar stores
        int cbase = i << 2;
        __stcs(mout + cbase + 0, mv[0]);
        __stcs(mout + cbase + 1, mv[1]);
        __stcs(mout + cbase + 2, mv[2]);
        __stcs(mout + cbase + 3, mv[3]);

        unsigned dv = (unsigned)(tgti - cbase);
        if (dv < 4u) {
            s_xt[0] = x0v[dv]; s_xt[1] = x1v[dv];
            s_xt[2] = x2v[dv]; s_xt[3] = x3v[dv];
        }

        a = a2; bq = bq2; cq = cq2; dq = dq2;
        i = ni;
    }

    // gather 26 partials
    float r[26];
#pragma unroll
    for (int j = 0; j < 4; j++) {
        r[j] = z1[j]; r[4 + j] = zs[j]; r[8 + j] = zt[j]; r[12 + j] = wt[j];
    }
#pragma unroll
    for (int d = 0; d < 10; d++) r[16 + d] = D[d];

    // warp tree-reduce (plain sums)
    const unsigned FULL = 0xffffffffu;
#pragma unroll
    for (int off = 16; off > 0; off >>= 1)
#pragma unroll
        for (int k = 0; k < 26; k++)
            r[k] += __shfl_down_sync(FULL, r[k], off);

    int lane = tid & 31, wid = tid >> 5;
    if (lane == 0)
#pragma unroll
        for (int k = 0; k < 26; k++) sred[wid][k] = r[k];
    __syncthreads();

    if (tid == 0) {
        for (int w = 1; w < NWARPS; w++)
#pragma unroll
            for (int k = 0; k < 26; k++) r[k] += sred[w][k];

        float xt[4] = {s_xt[0], s_xt[1], s_xt[2], s_xt[3]};
        const float invC = 1.0f / (float)C;
        float CE[4], KD[4];
#pragma unroll
        for (int j = 0; j < 4; j++) {
            float lse1 = lg_(r[j]);          // logsumexp(x),   M=0
            float lses = lg_(r[4 + j]);      // logsumexp(x/T)
            float lset = lg_(r[8 + j]);      // logsumexp(t/T)
            CE[j] = lse1 - xt[j];
            float S = r[12 + j] / r[8 + j];  // sum_c p_t*(m - x)
            KD[j] = 9.0f * invC * ((0.2f / 3.f) * S + lses - lset);
        }

        // DAL: deleting target entry == subtract xt_j*xt_k from dot accums
        float dd[10];
        int idx = 0;
#pragma unroll
        for (int j = 0; j < 4; j++)
#pragma unroll
            for (int k = j; k < 4; k++) { dd[idx] = r[16 + idx] - xt[j] * xt[k]; idx++; }
        float n0 = sqrtf(dd[0]), n1 = sqrtf(dd[4]), n2 = sqrtf(dd[7]), n3 = sqrtf(dd[9]);
        float dal = dd[1] / (n0 * n1) + dd[2] / (n0 * n2) + dd[3] / (n0 * n3)
                  + dd[5] / (n1 * n2) + dd[6] / (n1 * n3) + dd[8] / (n2 * n3);

        float irm = 0.f, mn = 3.402823466e38f;
#pragma unroll
        for (int j = 0; j < 4; j++) { irm += CE[j] + KD[j]; mn = fminf(mn, CE[j]); }
        g_L[b] = irm + 0.7f * mn + 0.3f * dal;
    }

    // ---- grid-wide finalize: last CTA to finish computes the mean ----
    __threadfence();
    if (tid == 0) {
        unsigned v = atomicAdd(&g_cnt, 1u);
        s_last = (v == (unsigned)(gridDim.x - 1));
    }
    __syncthreads();
    if (s_last) {
        __threadfence();  // acquire: see all g_L writes
        __shared__ float sf[NTHREADS];
        float acc = 0.f;
        for (int i2 = tid; i2 < B; i2 += NTHREADS) acc += g_L[i2];
        sf[tid] = acc;
        __syncthreads();
        for (int st = NTHREADS / 2; st > 0; st >>= 1) {
            if (tid < st) sf[tid] += sf[tid + st];
            __syncthreads();
        }
        if (tid == 0) {
            out[0] = sf[0] / (float)B;
            g_cnt = 0;  // reset for next replay (deterministic)
        }
    }
}

extern "C" void kernel_launch(void* const* d_in, const int* in_sizes, int n_in,
                              void* d_out, int out_size) {
    const float* o0 = (const float*)d_in[0];
    const float* o1 = (const float*)d_in[1];
    const float* o2 = (const float*)d_in[2];
    const float* o3 = (const float*)d_in[3];
    const void*  tg = d_in[4];
    const int B = in_sizes[4];
    const int C = in_sizes[0] / B;
    float* out = (float*)d_out;

    aed_fused_kernel<<<B, NTHREADS>>>(o0, o1, o2, o3, tg, out, C, B);
}

// round 6
// speedup vs baseline: 1.7155x; 1.1896x over previous
#include <cuda_runtime.h>
#include <cstdint>

#define NTHREADS 256
#define NWARPS   (NTHREADS / 32)

// Per-row loss scratch + completion counter (device globals: allocation-free).
__device__ float    g_L[4096];
__device__ unsigned g_cnt = 0;

__device__ __forceinline__ float ex2f_(float a) {
    float r; asm("ex2.approx.ftz.f32 %0, %1;" : "=f"(r) : "f"(a)); return r;
}
__device__ __forceinline__ float lg_(float a) {  // natural log
    float r; asm("lg2.approx.ftz.f32 %0, %1;" : "=f"(r) : "f"(a));
    return r * 0.6931471805599453f;
}

__global__ __launch_bounds__(NTHREADS, 3)
void aed_fused_kernel(const float* __restrict__ o0, const float* __restrict__ o1,
                      const float* __restrict__ o2, const float* __restrict__ o3,
                      const void* __restrict__ targets,
                      float* __restrict__ out, int C, int B)
{
    __shared__ float s_xt[4];
    __shared__ float sred[NWARPS][26];
    __shared__ int   s_last;

    const int b   = blockIdx.x;
    const int tid = threadIdx.x;

    // ---- targets-dtype detect + target-logit extract (once per CTA) ----
    if (tid < 32) {
        const int* t32 = (const int*)targets;
        int n = B < 128 ? B : 128;
        bool ok = true;
        for (int i = tid; i < n; i += 32) ok &= (t32[2 * i + 1] == 0);
        unsigned msk = __ballot_sync(0xffffffffu, ok);
        bool is64 = (msk == 0xffffffffu);
        if (tid == 0) {
            int tgti = is64 ? (int)(((const long long*)targets)[b])
                            : ((const int*)targets)[b];
            size_t off = (size_t)b * C + tgti;
            s_xt[0] = __ldg(o0 + off);
            s_xt[1] = __ldg(o1 + off);
            s_xt[2] = __ldg(o2 + off);
            s_xt[3] = __ldg(o3 + off);
        }
    }

    const float4* p0 = (const float4*)(o0 + (size_t)b * C);
    const float4* p1 = (const float4*)(o1 + (size_t)b * C);
    const float4* p2 = (const float4*)(o2 + (size_t)b * C);
    const float4* p3 = (const float4*)(o3 + (size_t)b * C);
    float* mout = out + 1 + (size_t)b * C;  // mimic row; 4-byte aligned ONLY

    const float K   = 0.48089834696298783f;   // log2(e)/3
    const float K02 = 0.2f * 0.48089834696298783f;

    // accumulators: z1 = sum e^x, zs = sum e^(x/3), zt = sum e^(t/3),
    // wt = sum e^(t/3)*(m-x), D = Gram dots
    float z1[4], zs[4], zt[4], wt[4], D[10];
#pragma unroll
    for (int j = 0; j < 4; j++) { z1[j] = 0.f; zs[j] = 0.f; zt[j] = 0.f; wt[j] = 0.f; }
#pragma unroll
    for (int d = 0; d < 10; d++) D[d] = 0.f;

    const int C4 = C >> 2;

    for (int i = tid; i < C4; i += NTHREADS) {
        float4 a  = __ldcs(p0 + i);
        float4 bq = __ldcs(p1 + i);
        float4 cq = __ldcs(p2 + i);
        float4 dq = __ldcs(p3 + i);

        float x0v[4] = {a.x,  a.y,  a.z,  a.w};
        float x1v[4] = {bq.x, bq.y, bq.z, bq.w};
        float x2v[4] = {cq.x, cq.y, cq.z, cq.w};
        float x3v[4] = {dq.x, dq.y, dq.z, dq.w};
        float mv[4];

#pragma unroll
        for (int v = 0; v < 4; v++) {
            float x0 = x0v[v], x1 = x1v[v], x2 = x2v[v], x3 = x3v[v];
            float m = 0.25f * ((x0 + x1) + (x2 + x3));
            mv[v] = m;
            float km02 = m * K02;

            D[0] = fmaf(x0, x0, D[0]);
            D[1] = fmaf(x0, x1, D[1]);
            D[2] = fmaf(x0, x2, D[2]);
            D[3] = fmaf(x0, x3, D[3]);
            D[4] = fmaf(x1, x1, D[4]);
            D[5] = fmaf(x1, x2, D[5]);
            D[6] = fmaf(x1, x3, D[6]);
            D[7] = fmaf(x2, x2, D[7]);
            D[8] = fmaf(x2, x3, D[8]);
            D[9] = fmaf(x3, x3, D[9]);

            float xj[4] = {x0, x1, x2, x3};
#pragma unroll
            for (int j = 0; j < 4; j++) {
                float x    = xj[j];
                float arg3 = x * K;                      // x/3 * log2e
                float argT = fmaf(0.8f, arg3, km02);     // t/3 * log2e
                float e  = ex2f_(arg3);                  // exp(x/3)
                float et = ex2f_(argT);                  // exp(t/3)
                float e3 = e * e * e;                    // exp(x) via cube (MUFU->FMA)
                z1[j] += e3;
                zs[j] += e;
                zt[j] += et;
                wt[j]  = fmaf(et, m - x, wt[j]);
            }
        }

        // mimic row base is out+1 -> 4-byte aligned only: scalar stores
        int cbase = i << 2;
        __stcs(mout + cbase + 0, mv[0]);
        __stcs(mout + cbase + 1, mv[1]);
        __stcs(mout + cbase + 2, mv[2]);
        __stcs(mout + cbase + 3, mv[3]);
    }

    // gather 26 partials
    float r[26];
#pragma unroll
    for (int j = 0; j < 4; j++) {
        r[j] = z1[j]; r[4 + j] = zs[j]; r[8 + j] = zt[j]; r[12 + j] = wt[j];
    }
#pragma unroll
    for (int d = 0; d < 10; d++) r[16 + d] = D[d];

    // warp tree-reduce (plain sums)
    const unsigned FULL = 0xffffffffu;
#pragma unroll
    for (int off = 16; off > 0; off >>= 1)
#pragma unroll
        for (int k = 0; k < 26; k++)
            r[k] += __shfl_down_sync(FULL, r[k], off);

    int lane = tid & 31, wid = tid >> 5;
    if (lane == 0)
#pragma unroll
        for (int k = 0; k < 26; k++) sred[wid][k] = r[k];
    __syncthreads();

    if (tid == 0) {
        for (int w = 1; w < NWARPS; w++)
#pragma unroll
            for (int k = 0; k < 26; k++) r[k] += sred[w][k];

        float xt[4] = {s_xt[0], s_xt[1], s_xt[2], s_xt[3]};
        const float invC = 1.0f / (float)C;
        float CE[4], KD[4];
#pragma unroll
        for (int j = 0; j < 4; j++) {
            float lse1 = lg_(r[j]);          // logsumexp(x),   M=0
            float lses = lg_(r[4 + j]);      // logsumexp(x/T)
            float lset = lg_(r[8 + j]);      // logsumexp(t/T)
            CE[j] = lse1 - xt[j];
            float S = r[12 + j] / r[8 + j];  // sum_c p_t*(m - x)
            KD[j] = 9.0f * invC * ((0.2f / 3.f) * S + lses - lset);
        }

        // DAL: deleting target entry == subtract xt_j*xt_k from dot accums
        float dd[10];
        int idx = 0;
#pragma unroll
        for (int j = 0; j < 4; j++)
#pragma unroll
            for (int k = j; k < 4; k++) { dd[idx] = r[16 + idx] - xt[j] * xt[k]; idx++; }
        float n0 = sqrtf(dd[0]), n1 = sqrtf(dd[4]), n2 = sqrtf(dd[7]), n3 = sqrtf(dd[9]);
        float dal = dd[1] / (n0 * n1) + dd[2] / (n0 * n2) + dd[3] / (n0 * n3)
                  + dd[5] / (n1 * n2) + dd[6] / (n1 * n3) + dd[8] / (n2 * n3);

        float irm = 0.f, mn = 3.402823466e38f;
#pragma unroll
        for (int j = 0; j < 4; j++) { irm += CE[j] + KD[j]; mn = fminf(mn, CE[j]); }
        g_L[b] = irm + 0.7f * mn + 0.3f * dal;
    }

    // ---- grid-wide finalize: last CTA to finish computes the mean ----
    __threadfence();
    if (tid == 0) {
        unsigned v = atomicAdd(&g_cnt, 1u);
        s_last = (v == (unsigned)(gridDim.x - 1));
    }
    __syncthreads();
    if (s_last) {
        __threadfence();  // acquire: see all g_L writes
        __shared__ float sf[NTHREADS];
        float acc = 0.f;
        for (int i2 = tid; i2 < B; i2 += NTHREADS) acc += g_L[i2];
        sf[tid] = acc;
        __syncthreads();
        for (int st = NTHREADS / 2; st > 0; st >>= 1) {
            if (tid < st) sf[tid] += sf[tid + st];
            __syncthreads();
        }
        if (tid == 0) {
            out[0] = sf[0] / (float)B;
            g_cnt = 0;  // reset for next replay (deterministic)
        }
    }
}

extern "C" void kernel_launch(void* const* d_in, const int* in_sizes, int n_in,
                              void* d_out, int out_size) {
    const float* o0 = (const float*)d_in[0];
    const float* o1 = (const float*)d_in[1];
    const float* o2 = (const float*)d_in[2];
    const float* o3 = (const float*)d_in[3];
    const void*  tg = d_in[4];
    const int B = in_sizes[4];
    const int C = in_sizes[0] / B;
    float* out = (float*)d_out;

    aed_fused_kernel<<<B, NTHREADS>>>(o0, o1, o2, o3, tg, out, C, B);
}

// round 7
// speedup vs baseline: 1.9057x; 1.1108x over previous
#include <cuda_runtime.h>
#include <cstdint>

#define NTHREADS 256
#define NWARPS   (NTHREADS / 32)

// Per-row loss scratch + completion counter (device globals: allocation-free).
__device__ float    g_L[4096];
__device__ unsigned g_cnt = 0;

__device__ __forceinline__ float ex2f_(float a) {
    float r; asm("ex2.approx.ftz.f32 %0, %1;" : "=f"(r) : "f"(a)); return r;
}
__device__ __forceinline__ float lg_(float a) {  // natural log
    float r; asm("lg2.approx.ftz.f32 %0, %1;" : "=f"(r) : "f"(a));
    return r * 0.6931471805599453f;
}

__global__ __launch_bounds__(NTHREADS, 4)
void aed_fused_kernel(const float* __restrict__ o0, const float* __restrict__ o1,
                      const float* __restrict__ o2, const float* __restrict__ o3,
                      const void* __restrict__ targets,
                      float* __restrict__ out, int C, int B)
{
    __shared__ float s_xt[4];
    __shared__ float sred[NWARPS][26];
    __shared__ int   s_last;

    const int b   = blockIdx.x;
    const int tid = threadIdx.x;

    // ---- targets-dtype detect + target-logit extract (once per CTA) ----
    if (tid < 32) {
        const int* t32 = (const int*)targets;
        int n = B < 128 ? B : 128;
        bool ok = true;
        for (int i = tid; i < n; i += 32) ok &= (t32[2 * i + 1] == 0);
        unsigned msk = __ballot_sync(0xffffffffu, ok);
        bool is64 = (msk == 0xffffffffu);
        if (tid == 0) {
            int tgti = is64 ? (int)(((const long long*)targets)[b])
                            : ((const int*)targets)[b];
            size_t off = (size_t)b * C + tgti;
            s_xt[0] = __ldg(o0 + off);
            s_xt[1] = __ldg(o1 + off);
            s_xt[2] = __ldg(o2 + off);
            s_xt[3] = __ldg(o3 + off);
        }
    }

    const float4* p0 = (const float4*)(o0 + (size_t)b * C);
    const float4* p1 = (const float4*)(o1 + (size_t)b * C);
    const float4* p2 = (const float4*)(o2 + (size_t)b * C);
    const float4* p3 = (const float4*)(o3 + (size_t)b * C);
    float* mout = out + 1 + (size_t)b * C;  // mimic row; 4-byte aligned ONLY

    const float K    = 0.48089834696298783f;          // log2(e)/3
    const float KS02 = 0.25f * 0.2f * 0.48089834696298783f;  // 0.25*0.2*K (applied to raw sum)

    // accumulators: z1 = sum e^x, zs = sum e^(x/3), zt = sum e^(t/3),
    // wt = sum e^(t/3)*(m-x), D = Gram dots
    float z1[4], zs[4], zt[4], wt[4], D[10];
#pragma unroll
    for (int j = 0; j < 4; j++) { z1[j] = 0.f; zs[j] = 0.f; zt[j] = 0.f; wt[j] = 0.f; }
#pragma unroll
    for (int d = 0; d < 10; d++) D[d] = 0.f;

    const int C4 = C >> 2;

    for (int i = tid; i < C4; i += NTHREADS) {
        float4 a  = __ldcs(p0 + i);
        float4 bq = __ldcs(p1 + i);
        float4 cq = __ldcs(p2 + i);
        float4 dq = __ldcs(p3 + i);

        float x0v[4] = {a.x,  a.y,  a.z,  a.w};
        float x1v[4] = {bq.x, bq.y, bq.z, bq.w};
        float x2v[4] = {cq.x, cq.y, cq.z, cq.w};
        float x3v[4] = {dq.x, dq.y, dq.z, dq.w};
        float mv[4];

#pragma unroll
        for (int v = 0; v < 4; v++) {
            float x0 = x0v[v], x1 = x1v[v], x2 = x2v[v], x3 = x3v[v];
            float sum = (x0 + x1) + (x2 + x3);
            float m = 0.25f * sum;
            mv[v] = m;
            float km02 = sum * KS02;   // = 0.2*K*m, one mul off the raw sum

            D[0] = fmaf(x0, x0, D[0]);
            D[1] = fmaf(x0, x1, D[1]);
            D[2] = fmaf(x0, x2, D[2]);
            D[3] = fmaf(x0, x3, D[3]);
            D[4] = fmaf(x1, x1, D[4]);
            D[5] = fmaf(x1, x2, D[5]);
            D[6] = fmaf(x1, x3, D[6]);
            D[7] = fmaf(x2, x2, D[7]);
            D[8] = fmaf(x2, x3, D[8]);
            D[9] = fmaf(x3, x3, D[9]);

            float xj[4] = {x0, x1, x2, x3};
#pragma unroll
            for (int j = 0; j < 4; j++) {
                float x    = xj[j];
                float arg3 = x * K;                      // x/3 * log2e
                float argT = fmaf(0.8f, arg3, km02);     // t/3 * log2e
                float e  = ex2f_(arg3);                  // exp(x/3)
                float et = ex2f_(argT);                  // exp(t/3)
                float e3 = e * e * e;                    // exp(x) via cube (MUFU->FMA)
                z1[j] += e3;
                zs[j] += e;
                zt[j] += et;
                wt[j]  = fmaf(et, m - x, wt[j]);
            }
        }

        // mimic row base is out+1 -> 4-byte aligned only: scalar stores
        int cbase = i << 2;
        __stcs(mout + cbase + 0, mv[0]);
        __stcs(mout + cbase + 1, mv[1]);
        __stcs(mout + cbase + 2, mv[2]);
        __stcs(mout + cbase + 3, mv[3]);
    }

    // gather 26 partials
    float r[26];
#pragma unroll
    for (int j = 0; j < 4; j++) {
        r[j] = z1[j]; r[4 + j] = zs[j]; r[8 + j] = zt[j]; r[12 + j] = wt[j];
    }
#pragma unroll
    for (int d = 0; d < 10; d++) r[16 + d] = D[d];

    // warp tree-reduce (plain sums)
    const unsigned FULL = 0xffffffffu;
#pragma unroll
    for (int off = 16; off > 0; off >>= 1)
#pragma unroll
        for (int k = 0; k < 26; k++)
            r[k] += __shfl_down_sync(FULL, r[k], off);

    int lane = tid & 31, wid = tid >> 5;
    if (lane == 0)
#pragma unroll
        for (int k = 0; k < 26; k++) sred[wid][k] = r[k];
    __syncthreads();

    if (tid == 0) {
        for (int w = 1; w < NWARPS; w++)
#pragma unroll
            for (int k = 0; k < 26; k++) r[k] += sred[w][k];

        float xt[4] = {s_xt[0], s_xt[1], s_xt[2], s_xt[3]};
        const float invC = 1.0f / (float)C;
        float CE[4], KD[4];
#pragma unroll
        for (int j = 0; j < 4; j++) {
            float lse1 = lg_(r[j]);          // logsumexp(x),   M=0
            float lses = lg_(r[4 + j]);      // logsumexp(x/T)
            float lset = lg_(r[8 + j]);      // logsumexp(t/T)
            CE[j] = lse1 - xt[j];
            float S = r[12 + j] / r[8 + j];  // sum_c p_t*(m - x)
            KD[j] = 9.0f * invC * ((0.2f / 3.f) * S + lses - lset);
        }

        // DAL: deleting target entry == subtract xt_j*xt_k from dot accums
        float dd[10];
        int idx = 0;
#pragma unroll
        for (int j = 0; j < 4; j++)
#pragma unroll
            for (int k = j; k < 4; k++) { dd[idx] = r[16 + idx] - xt[j] * xt[k]; idx++; }
        float n0 = sqrtf(dd[0]), n1 = sqrtf(dd[4]), n2 = sqrtf(dd[7]), n3 = sqrtf(dd[9]);
        float dal = dd[1] / (n0 * n1) + dd[2] / (n0 * n2) + dd[3] / (n0 * n3)
                  + dd[5] / (n1 * n2) + dd[6] / (n1 * n3) + dd[8] / (n2 * n3);

        float irm = 0.f, mn = 3.402823466e38f;
#pragma unroll
        for (int j = 0; j < 4; j++) { irm += CE[j] + KD[j]; mn = fminf(mn, CE[j]); }
        g_L[b] = irm + 0.7f * mn + 0.3f * dal;
    }

    // ---- grid-wide finalize: last CTA to finish computes the mean ----
    __threadfence();
    if (tid == 0) {
        unsigned v = atomicAdd(&g_cnt, 1u);
        s_last = (v == (unsigned)(gridDim.x - 1));
    }
    __syncthreads();
    if (s_last) {
        __threadfence();  // acquire: see all g_L writes
        __shared__ float sf[NTHREADS];
        float acc = 0.f;
        for (int i2 = tid; i2 < B; i2 += NTHREADS) acc += g_L[i2];
        sf[tid] = acc;
        __syncthreads();
        for (int st = NTHREADS / 2; st > 0; st >>= 1) {
            if (tid < st) sf[tid] += sf[tid + st];
            __syncthreads();
        }
        if (tid == 0) {
            out[0] = sf[0] / (float)B;
            g_cnt = 0;  // reset for next replay (deterministic)
        }
    }
}

extern "C" void kernel_launch(void* const* d_in, const int* in_sizes, int n_in,
                              void* d_out, int out_size) {
    const float* o0 = (const float*)d_in[0];
    const float* o1 = (const float*)d_in[1];
    const float* o2 = (const float*)d_in[2];
    const float* o3 = (const float*)d_in[3];
    const void*  tg = d_in[4];
    const int B = in_sizes[4];
    const int C = in_sizes[0] / B;
    float* out = (float*)d_out;

    aed_fused_kernel<<<B, NTHREADS>>>(o0, o1, o2, o3, tg, out, C, B);
}